// round 12
// baseline (speedup 1.0000x reference)
#include <cuda_runtime.h>
#include <math.h>
#include <float.h>

#define B 8
#define S 512
#define H 768
#define NTOT (B*S*H)        // 3145728
#define NT4  (NTOT/4)       // 786432
#define GRID 768
#define STRIDE4 (GRID*256)  // 196608 ; NT4/STRIDE4 = 4 exactly
#define TS 64
#define TO 64
#define TC 16
#define NTILE 64            // (S/TS) * B

// scratch (no cudaMalloc allowed)
__device__ __align__(16) float g_y[NTOT];        // conv output [B][O][S]
__device__ float g_psum [NTILE * H];
__device__ float g_pssum[NTILE * H];
__device__ float g_scale[H];
__device__ float g_shift[H];
__device__ unsigned g_ctr   = 0;                 // last-block ticket
__device__ unsigned g_epoch = 0;                 // stats-done epoch

// ---------------------------------------------------------------------------
// Warp-parallel Gumbel straight-through gate. Called by warp 0 (all 32 lanes).
// Lanes 0-9 hold the 10 logits; 16-wide shfl_xor reductions.
// ---------------------------------------------------------------------------
__device__ __forceinline__ void gate_warp(const float* __restrict__ u,
                                          const float* __restrict__ arch,
                                          int lane, int& idx_out, float& w_out)
{
    const unsigned FULL = 0xffffffffu;
    bool act = (lane < 10);
    float a  = act ? arch[lane] : -FLT_MAX;
    float uu = act ? u[lane]    : 0.5f;

    // m = max(a)
    float m = a;
    #pragma unroll
    for (int off = 8; off > 0; off >>= 1)
        m = fmaxf(m, __shfl_xor_sync(FULL, m, off, 16));
    // se = sum exp(a-m)
    float e = act ? __expf(a - m) : 0.f;
    float se = e;
    #pragma unroll
    for (int off = 8; off > 0; off >>= 1)
        se += __shfl_xor_sync(FULL, se, off, 16);
    float lse = m + __logf(se);

    float uc  = fminf(fmaxf(uu, 1e-9f), 1.f - 1e-9f);
    float gum = -__logf(-__logf(uc));
    float lg  = act ? ((a - lse) + gum) * 0.1f : -FLT_MAX;   // /TEM, TEM=10

    float m2 = lg;
    #pragma unroll
    for (int off = 8; off > 0; off >>= 1)
        m2 = fmaxf(m2, __shfl_xor_sync(FULL, m2, off, 16));
    float p = act ? __expf(lg - m2) : 0.f;
    float s2 = p;
    #pragma unroll
    for (int off = 8; off > 0; off >>= 1)
        s2 += __shfl_xor_sync(FULL, s2, off, 16);

    // argmax with first-max (lowest index) tie-break
    float bp = p; int bi = act ? lane : 31;
    #pragma unroll
    for (int off = 8; off > 0; off >>= 1) {
        float op = __shfl_xor_sync(FULL, bp, off, 16);
        int   oi = __shfl_xor_sync(FULL, bi, off, 16);
        if (op > bp || (op == bp && oi < bi)) { bp = op; bi = oi; }
    }
    float pi = bp / s2;
    idx_out = bi;
    w_out = (1.f - pi) + pi;                       // straight-through fwd value
}

// ---------------------------------------------------------------------------
// Single persistent kernel. grid = 768 blocks x 256 threads, all resident
// (launch_bounds(256,6): 6 blocks/SM x 148 SMs = 888 >= 768).
// Cheap branches (0,1,2,9): prefetch 4 float4/thread BEFORE the gate; warp 0
// computes the gate once per block (warp-parallel) while other warps' loads
// are in flight; broadcast via shared + one barrier; elementwise + store.
// Heavy branches (3..8): 1 conv tile per block, last-block BN stats, epoch
// spin, fused finalize.
// ---------------------------------------------------------------------------
__global__ __launch_bounds__(256, 6) void main_k(
    const float* __restrict__ x,
    const float* __restrict__ u,   const float* __restrict__ arch,
    const float* __restrict__ wn3, const float* __restrict__ wn5, const float* __restrict__ wn7,
    const float* __restrict__ wd3, const float* __restrict__ wd5, const float* __restrict__ wd7,
    const float* __restrict__ wp3, const float* __restrict__ wp5, const float* __restrict__ wp7,
    const float* __restrict__ g3,  const float* __restrict__ b3,
    const float* __restrict__ g5,  const float* __restrict__ b5,
    const float* __restrict__ g7,  const float* __restrict__ b7,
    const float* __restrict__ gd3, const float* __restrict__ bd3,
    const float* __restrict__ gd5, const float* __restrict__ bd5,
    const float* __restrict__ gd7, const float* __restrict__ bd7,
    float* __restrict__ out)
{
    __shared__ int   s_idx;
    __shared__ float s_w;
    int tid  = threadIdx.x;
    int bid  = blockIdx.x;
    int lane = tid & 31;
    int base = bid * 256 + tid;

    const float4* x4 = (const float4*)x;
    float4* o4 = (float4*)out;

    // ---- prefetch 4 float4 (independent of gate) ----
    float4 v[4];
    #pragma unroll
    for (int j = 0; j < 4; j++) v[j] = x4[base + j * STRIDE4];

    // ---- per-block warp-parallel gate, hidden under load latency ----
    if (tid < 32) {
        int ii; float ww;
        gate_warp(u, arch, lane, ii, ww);
        if (lane == 0) { s_idx = ii; s_w = ww; }
    }
    __syncthreads();
    int idx = s_idx;
    float w = s_w;

    if (idx < 3 || idx > 8) {
        // ---------------- cheap path ----------------
        if (idx == 0) {
            #pragma unroll
            for (int j = 0; j < 4; j++) o4[base + j * STRIDE4] = v[j];
        } else if (idx == 9) {
            #pragma unroll
            for (int j = 0; j < 4; j++) {
                float4 r;
                r.x = fmaf(w, v[j].x, v[j].x); r.y = fmaf(w, v[j].y, v[j].y);
                r.z = fmaf(w, v[j].z, v[j].z); r.w = fmaf(w, v[j].w, v[j].w);
                o4[base + j * STRIDE4] = r;
            }
        } else {
            float pad = (idx == 1) ? 0.f : -INFINITY;
            #pragma unroll
            for (int j = 0; j < 4; j++) {
                int i4 = base + j * STRIDE4;
                int s = (i4 / (H / 4)) % S;
                float4 xv = v[j];
                float4 l  = make_float4(pad, pad, pad, pad);
                float4 rr = l;
                if (s > 0)     l  = x4[i4 - H / 4];
                if (s < S - 1) rr = x4[i4 + H / 4];
                float4 r;
                if (idx == 1) {
                    r.x = fmaf(w, (l.x + xv.x + rr.x) * (1.f / 3.f), xv.x);
                    r.y = fmaf(w, (l.y + xv.y + rr.y) * (1.f / 3.f), xv.y);
                    r.z = fmaf(w, (l.z + xv.z + rr.z) * (1.f / 3.f), xv.z);
                    r.w = fmaf(w, (l.w + xv.w + rr.w) * (1.f / 3.f), xv.w);
                } else {
                    r.x = fmaf(w, fmaxf(fmaxf(l.x, xv.x), rr.x), xv.x);
                    r.y = fmaf(w, fmaxf(fmaxf(l.y, xv.y), rr.y), xv.y);
                    r.z = fmaf(w, fmaxf(fmaxf(l.z, xv.z), rr.z), xv.z);
                    r.w = fmaf(w, fmaxf(fmaxf(l.w, xv.w), rr.w), xv.w);
                }
                o4[i4] = r;
            }
        }
        return;
    }

    // ---------------- heavy path: 1 conv tile per block ----------------
    __shared__ unsigned s_epoch;
    __shared__ int      s_last;
    if (tid == 0) s_epoch = *(volatile unsigned*)&g_epoch;  // before our ticket

    bool nor = (idx < 6);
    int k, pad_;
    const float* W;
    int kd = 0; const float* wd = nullptr;
    if (nor) {
        k = 3 + 2 * (idx - 3); pad_ = k / 2;
        W = (idx == 3) ? wn3 : (idx == 4) ? wn5 : wn7;
    } else {
        k = 1; pad_ = 0;
        W = (idx == 6) ? wp3 : (idx == 7) ? wp5 : wp7;
        kd = 3 + 2 * (idx - 6);
        wd = (idx == 6) ? wd3 : (idx == 7) ? wd5 : wd7;
    }

    __shared__ float xs[TC][TS + 8];
    __shared__ float ws[7][TC][TO];
    int ts = tid & 15, to = tid >> 4;

    int tx = bid & 7;
    int ty = (bid >> 3) % 12;
    int b  = bid / 96;
    int S0 = tx * TS;
    int O0 = ty * TO;

    float acc[4][4];
    #pragma unroll
    for (int i = 0; i < 4; i++)
        #pragma unroll
        for (int j = 0; j < 4; j++) acc[i][j] = 0.f;

    for (int c0 = 0; c0 < H; c0 += TC) {
        for (int i = tid; i < TC * (TS + 6); i += 256) {
            int c = i & 15;
            int s = i >> 4;
            int sp = S0 + s - pad_;
            float vv = 0.f;
            if (sp >= 0 && sp < S) {
                if (nor) {
                    vv = fmaxf(x[(b * S + sp) * H + (c0 + c)], 0.f);
                } else {
                    float a2 = 0.f;
                    for (int t = 0; t < kd; t++) {
                        int spp = sp - (kd - 1) + 2 * t;
                        if (spp >= 0 && spp < S)
                            a2 += fmaxf(x[(b * S + spp) * H + (c0 + c)], 0.f)
                                  * wd[(c0 + c) * kd + t];
                    }
                    vv = a2;
                }
            }
            xs[c][s] = vv;
        }
        int tot = k * TC * TO;
        for (int i = tid; i < tot; i += 256) {
            int o = i & 63;
            int r = i >> 6;
            int c = r & 15;
            int t = r >> 4;
            float wv = nor ? W[((O0 + o) * H + (c0 + c)) * k + t]
                           : W[(O0 + o) * H + (c0 + c)];
            ws[t][c][o] = wv;
        }
        __syncthreads();

        for (int t = 0; t < k; t++) {
            #pragma unroll
            for (int c = 0; c < TC; c++) {
                float a0 = xs[c][ts * 4 + 0 + t];
                float a1 = xs[c][ts * 4 + 1 + t];
                float a2 = xs[c][ts * 4 + 2 + t];
                float a3 = xs[c][ts * 4 + 3 + t];
                float4 wv = *(const float4*)&ws[t][c][to * 4];
                acc[0][0] += a0 * wv.x; acc[0][1] += a0 * wv.y;
                acc[0][2] += a0 * wv.z; acc[0][3] += a0 * wv.w;
                acc[1][0] += a1 * wv.x; acc[1][1] += a1 * wv.y;
                acc[1][2] += a1 * wv.z; acc[1][3] += a1 * wv.w;
                acc[2][0] += a2 * wv.x; acc[2][1] += a2 * wv.y;
                acc[2][2] += a2 * wv.z; acc[2][3] += a2 * wv.w;
                acc[3][0] += a3 * wv.x; acc[3][1] += a3 * wv.y;
                acc[3][2] += a3 * wv.z; acc[3][3] += a3 * wv.w;
            }
        }
        __syncthreads();
    }

    // write y tile + BN partial sums (deterministic, no atomics)
    int tile = b * 8 + tx;                 // 0..63
    #pragma unroll
    for (int j = 0; j < 4; j++) {
        int o = O0 + to * 4 + j;
        float4 vv = make_float4(acc[0][j], acc[1][j], acc[2][j], acc[3][j]);
        *(float4*)&g_y[(b * H + o) * S + S0 + ts * 4] = vv;

        float ps  = acc[0][j] + acc[1][j] + acc[2][j] + acc[3][j];
        float pss = acc[0][j]*acc[0][j] + acc[1][j]*acc[1][j]
                  + acc[2][j]*acc[2][j] + acc[3][j]*acc[3][j];
        #pragma unroll
        for (int off = 8; off > 0; off >>= 1) {
            ps  += __shfl_down_sync(0xffffffffu, ps,  off, 16);
            pss += __shfl_down_sync(0xffffffffu, pss, off, 16);
        }
        if (ts == 0) {
            g_psum [tile * H + o] = ps;
            g_pssum[tile * H + o] = pss;
        }
    }

    // ----- chip-wide: last block computes BN scale/shift -----
    __threadfence();
    __syncthreads();
    if (tid == 0) {
        unsigned t = atomicAdd(&g_ctr, 1u);
        s_last = (t == GRID - 1);
    }
    __syncthreads();

    if (s_last) {
        const float* gamma; const float* beta;
        switch (idx) {
            case 3: gamma = g3;  beta = b3;  break;
            case 4: gamma = g5;  beta = b5;  break;
            case 5: gamma = g7;  beta = b7;  break;
            case 6: gamma = gd3; beta = bd3; break;
            case 7: gamma = gd5; beta = bd5; break;
            default: gamma = gd7; beta = bd7; break;
        }
        #pragma unroll
        for (int q = 0; q < 3; q++) {
            int o = tid + q * 256;
            float s1 = 0.f, s2 = 0.f;
            for (int t = 0; t < NTILE; t++) {
                s1 += g_psum [t * H + o];
                s2 += g_pssum[t * H + o];
            }
            float mean = s1 * (1.f / 4096.f);
            float var  = s2 * (1.f / 4096.f) - mean * mean;
            float sc = rsqrtf(var + 1e-5f) * gamma[o];
            g_scale[o] = sc;
            g_shift[o] = beta[o] - mean * sc;
        }
        __syncthreads();
        __threadfence();
        if (tid == 0) {
            g_ctr = 0;                         // reset for next replay
            __threadfence();
            atomicAdd(&g_epoch, 1u);           // release
        }
    } else {
        if (tid == 0) {
            unsigned old = s_epoch;
            while (*(volatile unsigned*)&g_epoch == old) { __nanosleep(64); }
        }
        __syncthreads();
        __threadfence();
    }

    // ----- finalize: BN apply + gate weight + residual + transpose -----
    #pragma unroll
    for (int j = 0; j < 4; j++) {
        int i4 = base + j * STRIDE4;
        int h = (i4 % (H / 4)) * 4;
        int s = (i4 / (H / 4)) % S;
        int b2 = i4 / ((H / 4) * S);
        float4 xv = x4[i4];
        float4 r;
        r.x = fmaf(w, fmaf(g_y[(b2 * H + h + 0) * S + s], g_scale[h + 0], g_shift[h + 0]), xv.x);
        r.y = fmaf(w, fmaf(g_y[(b2 * H + h + 1) * S + s], g_scale[h + 1], g_shift[h + 1]), xv.y);
        r.z = fmaf(w, fmaf(g_y[(b2 * H + h + 2) * S + s], g_scale[h + 2], g_shift[h + 2]), xv.z);
        r.w = fmaf(w, fmaf(g_y[(b2 * H + h + 3) * S + s], g_scale[h + 3], g_shift[h + 3]), xv.w);
        o4[i4] = r;
    }
}

// ---------------------------------------------------------------------------
extern "C" void kernel_launch(void* const* d_in, const int* in_sizes, int n_in,
                              void* d_out, int out_size)
{
    const float* x    = (const float*)d_in[0];
    const float* u    = (const float*)d_in[1];
    const float* arch = (const float*)d_in[2];
    const float* wn3 = (const float*)d_in[3];
    const float* gn3 = (const float*)d_in[4];
    const float* bn3 = (const float*)d_in[5];
    const float* wn5 = (const float*)d_in[6];
    const float* gn5 = (const float*)d_in[7];
    const float* bn5 = (const float*)d_in[8];
    const float* wn7 = (const float*)d_in[9];
    const float* gn7 = (const float*)d_in[10];
    const float* bn7 = (const float*)d_in[11];
    const float* wd3 = (const float*)d_in[12];
    const float* wp3 = (const float*)d_in[13];
    const float* gd3 = (const float*)d_in[14];
    const float* bd3 = (const float*)d_in[15];
    const float* wd5 = (const float*)d_in[16];
    const float* wp5 = (const float*)d_in[17];
    const float* gd5 = (const float*)d_in[18];
    const float* bd5 = (const float*)d_in[19];
    const float* wd7 = (const float*)d_in[20];
    const float* wp7 = (const float*)d_in[21];
    const float* gd7 = (const float*)d_in[22];
    const float* bd7 = (const float*)d_in[23];
    float* out = (float*)d_out;

    main_k<<<GRID, 256>>>(x, u, arch,
                          wn3, wn5, wn7,
                          wd3, wd5, wd7,
                          wp3, wp5, wp7,
                          gn3, bn3, gn5, bn5, gn7, bn7,
                          gd3, bd3, gd5, bd5, gd7, bd7,
                          out);
}

// round 15
// speedup vs baseline: 1.2620x; 1.2620x over previous
#include <cuda_runtime.h>
#include <math.h>
#include <float.h>

#define B 8
#define S 512
#define H 768
#define NTOT (B*S*H)       // 3145728
#define NT4  (NTOT/4)      // 786432
#define GRID 512
#define STRIDE4 (GRID*256) // 131072 ; NT4 / STRIDE4 = 6 exactly
#define TS 64
#define TO 64
#define TC 16
#define NTILE 64           // (S/TS) * B

// scratch (no cudaMalloc allowed)
__device__ __align__(16) float g_y[NTOT];        // conv output [B][O][S]
__device__ float g_psum [NTILE * H];
__device__ float g_pssum[NTILE * H];
__device__ float g_scale[H];
__device__ float g_shift[H];
__device__ unsigned g_ctr   = 0;                 // last-block ticket
__device__ unsigned g_epoch = 0;                 // stats-done epoch

// ---------------------------------------------------------------------------
// Warp-parallel Gumbel straight-through gate (low register footprint).
// Called by all 32 lanes of warp 0; lanes 0-9 hold the 10 logits.
// ---------------------------------------------------------------------------
__device__ __forceinline__ void gate_warp(const float* __restrict__ u,
                                          const float* __restrict__ arch,
                                          int lane, int& idx_out, float& w_out)
{
    const unsigned FULL = 0xffffffffu;
    bool act = (lane < 10);
    float a  = act ? arch[lane] : -FLT_MAX;
    float uu = act ? u[lane]    : 0.5f;

    float m = a;
    #pragma unroll
    for (int off = 8; off > 0; off >>= 1)
        m = fmaxf(m, __shfl_xor_sync(FULL, m, off, 16));
    float se = act ? __expf(a - m) : 0.f;
    #pragma unroll
    for (int off = 8; off > 0; off >>= 1)
        se += __shfl_xor_sync(FULL, se, off, 16);
    float lse = m + __logf(se);

    float uc  = fminf(fmaxf(uu, 1e-9f), 1.f - 1e-9f);
    float gum = -__logf(-__logf(uc));
    float lg  = act ? ((a - lse) + gum) * 0.1f : -FLT_MAX;   // /TEM, TEM=10

    float m2 = lg;
    #pragma unroll
    for (int off = 8; off > 0; off >>= 1)
        m2 = fmaxf(m2, __shfl_xor_sync(FULL, m2, off, 16));
    float p = act ? __expf(lg - m2) : 0.f;
    float s2 = p;
    #pragma unroll
    for (int off = 8; off > 0; off >>= 1)
        s2 += __shfl_xor_sync(FULL, s2, off, 16);

    // argmax with lowest-index tie-break
    float bp = p; int bi = act ? lane : 31;
    #pragma unroll
    for (int off = 8; off > 0; off >>= 1) {
        float op = __shfl_xor_sync(FULL, bp, off, 16);
        int   oi = __shfl_xor_sync(FULL, bi, off, 16);
        if (op > bp || (op == bp && oi < bi)) { bp = op; bi = oi; }
    }
    float pi = bp / s2;
    idx_out = bi;
    w_out = (1.f - pi) + pi;                       // straight-through fwd value
}

// ---------------------------------------------------------------------------
// Single persistent kernel. grid = 512 blocks x 256 threads, all resident
// (launch_bounds(256,4): 4 blocks/SM x 148 SMs = 592 >= 512).
// Cheap branches (0,1,2,9): prefetch 6 float4/thread BEFORE the gate; warp 0
// computes the gate (warp-parallel, low-reg) while loads are in flight;
// broadcast via shared + one barrier; elementwise + store.
// Heavy branches (3..8): 1-2 conv tiles per block, last-block BN stats,
// epoch spin, fused finalize.
// ---------------------------------------------------------------------------
__global__ __launch_bounds__(256, 4) void main_k(
    const float* __restrict__ x,
    const float* __restrict__ u,   const float* __restrict__ arch,
    const float* __restrict__ wn3, const float* __restrict__ wn5, const float* __restrict__ wn7,
    const float* __restrict__ wd3, const float* __restrict__ wd5, const float* __restrict__ wd7,
    const float* __restrict__ wp3, const float* __restrict__ wp5, const float* __restrict__ wp7,
    const float* __restrict__ g3,  const float* __restrict__ b3,
    const float* __restrict__ g5,  const float* __restrict__ b5,
    const float* __restrict__ g7,  const float* __restrict__ b7,
    const float* __restrict__ gd3, const float* __restrict__ bd3,
    const float* __restrict__ gd5, const float* __restrict__ bd5,
    const float* __restrict__ gd7, const float* __restrict__ bd7,
    float* __restrict__ out)
{
    __shared__ int      s_idx;
    __shared__ float    s_w;
    __shared__ unsigned s_epoch;
    __shared__ int      s_last;
    int tid  = threadIdx.x;
    int bid  = blockIdx.x;
    int lane = tid & 31;
    int base = bid * 256 + tid;

    const float4* x4 = (const float4*)x;
    float4* o4 = (float4*)out;

    // ---- prefetch all 6 float4 (independent of gate) ----
    float4 v[6];
    #pragma unroll
    for (int j = 0; j < 6; j++) v[j] = x4[base + j * STRIDE4];

    // ---- per-block warp-parallel gate, hidden under load latency ----
    if (tid < 32) {
        int ii; float ww;
        gate_warp(u, arch, lane, ii, ww);
        if (lane == 0) {
            s_idx = ii; s_w = ww;
            s_epoch = *(volatile unsigned*)&g_epoch;   // before any ticket
        }
    }
    __syncthreads();
    int idx = s_idx;
    float w = s_w;

    if (idx < 3 || idx > 8) {
        // ---------------- cheap path ----------------
        if (idx == 0) {
            #pragma unroll
            for (int j = 0; j < 6; j++) o4[base + j * STRIDE4] = v[j];
        } else if (idx == 9) {
            #pragma unroll
            for (int j = 0; j < 6; j++) {
                float4 r;
                r.x = fmaf(w, v[j].x, v[j].x); r.y = fmaf(w, v[j].y, v[j].y);
                r.z = fmaf(w, v[j].z, v[j].z); r.w = fmaf(w, v[j].w, v[j].w);
                o4[base + j * STRIDE4] = r;
            }
        } else {
            float pad = (idx == 1) ? 0.f : -INFINITY;
            #pragma unroll
            for (int j = 0; j < 6; j++) {
                int i4 = base + j * STRIDE4;
                int s = (i4 / (H / 4)) % S;
                float4 xv = v[j];
                float4 l  = make_float4(pad, pad, pad, pad);
                float4 rr = l;
                if (s > 0)     l  = x4[i4 - H / 4];
                if (s < S - 1) rr = x4[i4 + H / 4];
                float4 r;
                if (idx == 1) {
                    r.x = fmaf(w, (l.x + xv.x + rr.x) * (1.f / 3.f), xv.x);
                    r.y = fmaf(w, (l.y + xv.y + rr.y) * (1.f / 3.f), xv.y);
                    r.z = fmaf(w, (l.z + xv.z + rr.z) * (1.f / 3.f), xv.z);
                    r.w = fmaf(w, (l.w + xv.w + rr.w) * (1.f / 3.f), xv.w);
                } else {
                    r.x = fmaf(w, fmaxf(fmaxf(l.x, xv.x), rr.x), xv.x);
                    r.y = fmaf(w, fmaxf(fmaxf(l.y, xv.y), rr.y), xv.y);
                    r.z = fmaf(w, fmaxf(fmaxf(l.z, xv.z), rr.z), xv.z);
                    r.w = fmaf(w, fmaxf(fmaxf(l.w, xv.w), rr.w), xv.w);
                }
                o4[i4] = r;
            }
        }
        return;
    }

    // ---------------- heavy path: tiled conv GEMM ----------------
    bool nor = (idx < 6);
    int k, pad_;
    const float* W;
    int kd = 0; const float* wd = nullptr;
    if (nor) {
        k = 3 + 2 * (idx - 3); pad_ = k / 2;
        W = (idx == 3) ? wn3 : (idx == 4) ? wn5 : wn7;
    } else {
        k = 1; pad_ = 0;
        W = (idx == 6) ? wp3 : (idx == 7) ? wp5 : wp7;
        kd = 3 + 2 * (idx - 6);
        wd = (idx == 6) ? wd3 : (idx == 7) ? wd5 : wd7;
    }

    __shared__ float xs[TC][TS + 8];
    __shared__ float ws[7][TC][TO];
    int ts = tid & 15, to = tid >> 4;

    for (int tt = bid; tt < 768; tt += GRID) {
        int tx = tt & 7;
        int ty = (tt >> 3) % 12;
        int b  = tt / 96;
        int S0 = tx * TS;
        int O0 = ty * TO;

        float acc[4][4];
        #pragma unroll
        for (int i = 0; i < 4; i++)
            #pragma unroll
            for (int j = 0; j < 4; j++) acc[i][j] = 0.f;

        for (int c0 = 0; c0 < H; c0 += TC) {
            for (int i = tid; i < TC * (TS + 6); i += 256) {
                int c = i & 15;
                int s = i >> 4;
                int sp = S0 + s - pad_;
                float vv = 0.f;
                if (sp >= 0 && sp < S) {
                    if (nor) {
                        vv = fmaxf(x[(b * S + sp) * H + (c0 + c)], 0.f);
                    } else {
                        float a2 = 0.f;
                        for (int t = 0; t < kd; t++) {
                            int spp = sp - (kd - 1) + 2 * t;
                            if (spp >= 0 && spp < S)
                                a2 += fmaxf(x[(b * S + spp) * H + (c0 + c)], 0.f)
                                      * wd[(c0 + c) * kd + t];
                        }
                        vv = a2;
                    }
                }
                xs[c][s] = vv;
            }
            int tot = k * TC * TO;
            for (int i = tid; i < tot; i += 256) {
                int o = i & 63;
                int r = i >> 6;
                int c = r & 15;
                int t = r >> 4;
                float wv = nor ? W[((O0 + o) * H + (c0 + c)) * k + t]
                               : W[(O0 + o) * H + (c0 + c)];
                ws[t][c][o] = wv;
            }
            __syncthreads();

            for (int t = 0; t < k; t++) {
                #pragma unroll
                for (int c = 0; c < TC; c++) {
                    float a0 = xs[c][ts * 4 + 0 + t];
                    float a1 = xs[c][ts * 4 + 1 + t];
                    float a2 = xs[c][ts * 4 + 2 + t];
                    float a3 = xs[c][ts * 4 + 3 + t];
                    float4 wv = *(const float4*)&ws[t][c][to * 4];
                    acc[0][0] += a0 * wv.x; acc[0][1] += a0 * wv.y;
                    acc[0][2] += a0 * wv.z; acc[0][3] += a0 * wv.w;
                    acc[1][0] += a1 * wv.x; acc[1][1] += a1 * wv.y;
                    acc[1][2] += a1 * wv.z; acc[1][3] += a1 * wv.w;
                    acc[2][0] += a2 * wv.x; acc[2][1] += a2 * wv.y;
                    acc[2][2] += a2 * wv.z; acc[2][3] += a2 * wv.w;
                    acc[3][0] += a3 * wv.x; acc[3][1] += a3 * wv.y;
                    acc[3][2] += a3 * wv.z; acc[3][3] += a3 * wv.w;
                }
            }
            __syncthreads();
        }

        // write y tile + BN partial sums (deterministic, no atomics)
        int tile = b * 8 + tx;                 // 0..63
        #pragma unroll
        for (int j = 0; j < 4; j++) {
            int o = O0 + to * 4 + j;
            float4 vv = make_float4(acc[0][j], acc[1][j], acc[2][j], acc[3][j]);
            *(float4*)&g_y[(b * H + o) * S + S0 + ts * 4] = vv;

            float ps  = acc[0][j] + acc[1][j] + acc[2][j] + acc[3][j];
            float pss = acc[0][j]*acc[0][j] + acc[1][j]*acc[1][j]
                      + acc[2][j]*acc[2][j] + acc[3][j]*acc[3][j];
            #pragma unroll
            for (int off = 8; off > 0; off >>= 1) {
                ps  += __shfl_down_sync(0xffffffffu, ps,  off, 16);
                pss += __shfl_down_sync(0xffffffffu, pss, off, 16);
            }
            if (ts == 0) {
                g_psum [tile * H + o] = ps;
                g_pssum[tile * H + o] = pss;
            }
        }
        __syncthreads();
    }

    // ----- chip-wide: last block computes BN scale/shift -----
    __threadfence();
    if (tid == 0) {
        unsigned t = atomicAdd(&g_ctr, 1u);
        s_last = (t == GRID - 1);
    }
    __syncthreads();

    if (s_last) {
        const float* gamma; const float* beta;
        switch (idx) {
            case 3: gamma = g3;  beta = b3;  break;
            case 4: gamma = g5;  beta = b5;  break;
            case 5: gamma = g7;  beta = b7;  break;
            case 6: gamma = gd3; beta = bd3; break;
            case 7: gamma = gd5; beta = bd5; break;
            default: gamma = gd7; beta = bd7; break;
        }
        #pragma unroll
        for (int q = 0; q < 3; q++) {
            int o = tid + q * 256;
            float s1 = 0.f, s2 = 0.f;
            for (int t = 0; t < NTILE; t++) {
                s1 += g_psum [t * H + o];
                s2 += g_pssum[t * H + o];
            }
            float mean = s1 * (1.f / 4096.f);
            float var  = s2 * (1.f / 4096.f) - mean * mean;
            float sc = rsqrtf(var + 1e-5f) * gamma[o];
            g_scale[o] = sc;
            g_shift[o] = beta[o] - mean * sc;
        }
        __syncthreads();
        __threadfence();
        if (tid == 0) {
            g_ctr = 0;                         // reset for next replay
            __threadfence();
            atomicAdd(&g_epoch, 1u);           // release
        }
    } else {
        if (tid == 0) {
            unsigned old = s_epoch;
            while (*(volatile unsigned*)&g_epoch == old) { __nanosleep(64); }
        }
        __syncthreads();
        __threadfence();
    }

    // ----- finalize: BN apply + gate weight + residual + transpose -----
    #pragma unroll
    for (int j = 0; j < 6; j++) {
        int i4 = base + j * STRIDE4;
        int h = (i4 % (H / 4)) * 4;
        int s = (i4 / (H / 4)) % S;
        int b2 = i4 / ((H / 4) * S);
        float4 xv = x4[i4];
        float4 r;
        r.x = fmaf(w, fmaf(g_y[(b2 * H + h + 0) * S + s], g_scale[h + 0], g_shift[h + 0]), xv.x);
        r.y = fmaf(w, fmaf(g_y[(b2 * H + h + 1) * S + s], g_scale[h + 1], g_shift[h + 1]), xv.y);
        r.z = fmaf(w, fmaf(g_y[(b2 * H + h + 2) * S + s], g_scale[h + 2], g_shift[h + 2]), xv.z);
        r.w = fmaf(w, fmaf(g_y[(b2 * H + h + 3) * S + s], g_scale[h + 3], g_shift[h + 3]), xv.w);
        o4[i4] = r;
    }
}

// ---------------------------------------------------------------------------
extern "C" void kernel_launch(void* const* d_in, const int* in_sizes, int n_in,
                              void* d_out, int out_size)
{
    const float* x    = (const float*)d_in[0];
    const float* u    = (const float*)d_in[1];
    const float* arch = (const float*)d_in[2];
    const float* wn3 = (const float*)d_in[3];
    const float* gn3 = (const float*)d_in[4];
    const float* bn3 = (const float*)d_in[5];
    const float* wn5 = (const float*)d_in[6];
    const float* gn5 = (const float*)d_in[7];
    const float* bn5 = (const float*)d_in[8];
    const float* wn7 = (const float*)d_in[9];
    const float* gn7 = (const float*)d_in[10];
    const float* bn7 = (const float*)d_in[11];
    const float* wd3 = (const float*)d_in[12];
    const float* wp3 = (const float*)d_in[13];
    const float* gd3 = (const float*)d_in[14];
    const float* bd3 = (const float*)d_in[15];
    const float* wd5 = (const float*)d_in[16];
    const float* wp5 = (const float*)d_in[17];
    const float* gd5 = (const float*)d_in[18];
    const float* bd5 = (const float*)d_in[19];
    const float* wd7 = (const float*)d_in[20];
    const float* wp7 = (const float*)d_in[21];
    const float* gd7 = (const float*)d_in[22];
    const float* bd7 = (const float*)d_in[23];
    float* out = (float*)d_out;

    main_k<<<GRID, 256>>>(x, u, arch,
                          wn3, wn5, wn7,
                          wd3, wd5, wd7,
                          wp3, wp5, wp7,
                          gn3, bn3, gn5, bn5, gn7, bn7,
                          gd3, bd3, gd5, bd5, gd7, bd7,
                          out);
}